// round 3
// baseline (speedup 1.0000x reference)
#include <cuda_runtime.h>
#include <cstdint>

// PRNG variant for replicating jax.random bits:
//  1: partitionable counter mode, bits = lane0 ^ lane1   (modern JAX default - primary guess)
//  2: partitionable, bits = lane0
//  3: partitionable, bits = lane1
//  0: original (non-partitionable) split-halves mode
#ifndef TF_VARIANT
#define TF_VARIANT 1
#endif

static constexpr int MAXN = 100352;

// Scratch (static device globals: allocation-free per harness rules)
__device__ float g_h0[MAXN];     // dropout1(x)
__device__ float g_deg[MAXN];    // in-degree (float)
__device__ float g_dinv[MAXN];   // deg^-1/2 (0 if deg==0)
__device__ float g_hd[MAXN];     // h0 * dinv  (gathered by pass1)
__device__ float g_acc1[MAXN];   // edge-sum for conv1
__device__ float g_sd[MAXN];     // s2 * dinv  (gathered by pass2)
__device__ float g_acc2[MAXN];   // edge-sum for conv2
__device__ unsigned char g_mask2[MAXN * 16]; // dropout2 keep flags

// keep  <=>  uniform(bits) < float32(0.4)  <=>  bits < 0x66666800
#define KEEP_THRESH 0x66666800u

__host__ __device__ __forceinline__ void tf2x32(uint32_t k0, uint32_t k1,
                                                uint32_t x0, uint32_t x1,
                                                uint32_t& o0, uint32_t& o1) {
    uint32_t ks2 = k0 ^ k1 ^ 0x1BD11BDAu;
    x0 += k0; x1 += k1;
#define TF_ROT(d) { x0 += x1; x1 = (x1 << (d)) | (x1 >> (32 - (d))); x1 ^= x0; }
    TF_ROT(13) TF_ROT(15) TF_ROT(26) TF_ROT(6)   x0 += k1;  x1 += ks2 + 1u;
    TF_ROT(17) TF_ROT(29) TF_ROT(16) TF_ROT(24)  x0 += ks2; x1 += k0 + 2u;
    TF_ROT(13) TF_ROT(15) TF_ROT(26) TF_ROT(6)   x0 += k0;  x1 += k1 + 3u;
    TF_ROT(17) TF_ROT(29) TF_ROT(16) TF_ROT(24)  x0 += k1;  x1 += ks2 + 4u;
    TF_ROT(13) TF_ROT(15) TF_ROT(26) TF_ROT(6)   x0 += ks2; x1 += k0 + 5u;
#undef TF_ROT
    o0 = x0; o1 = x1;
}

// 32-bit random word for flat element i of a draw with total (even) size `sz`.
__device__ __forceinline__ uint32_t rbits32(uint32_t k0, uint32_t k1,
                                            uint32_t i, uint32_t sz) {
    uint32_t a, b;
#if TF_VARIANT == 1
    tf2x32(k0, k1, 0u, i, a, b);
    (void)sz; return a ^ b;
#elif TF_VARIANT == 2
    tf2x32(k0, k1, 0u, i, a, b);
    (void)sz; return a;
#elif TF_VARIANT == 3
    tf2x32(k0, k1, 0u, i, a, b);
    (void)sz; return b;
#else
    uint32_t half = sz >> 1;
    if (i < half) { tf2x32(k0, k1, i, i + half, a, b); return a; }
    else          { tf2x32(k0, k1, i - half, i, a, b); return b; }
#endif
}

// ---------------- kernels ----------------

__global__ __launch_bounds__(256) void k_init(const float* __restrict__ x, int N,
                                              uint32_t k0, uint32_t k1) {
    int n = blockIdx.x * blockDim.x + threadIdx.x;
    if (n >= N) return;
    uint32_t bits = rbits32(k0, k1, (uint32_t)n, (uint32_t)N);
    g_h0[n]   = (bits < KEEP_THRESH) ? (x[n] / 0.4f) : 0.0f;
    g_deg[n]  = 0.0f;
    g_acc1[n] = 0.0f;
    g_acc2[n] = 0.0f;
}

__global__ __launch_bounds__(256) void k_mask2(int M, uint32_t k0, uint32_t k1) {
    int t = blockIdx.x * blockDim.x + threadIdx.x;
    if (t >= M) return;
    uint32_t bits = rbits32(k0, k1, (uint32_t)t, (uint32_t)M);
    g_mask2[t] = (bits < KEEP_THRESH) ? 1 : 0;
}

// degree pass: int32 dst indices, 4 edges per thread via int4
__global__ __launch_bounds__(256) void k_deg(const int* __restrict__ dst,
                                             int EV, int E) {
    int i = blockIdx.x * blockDim.x + threadIdx.x;
    if (i < EV) {
        int4 v = reinterpret_cast<const int4*>(dst)[i];
        atomicAdd(&g_deg[v.x], 1.0f);
        atomicAdd(&g_deg[v.y], 1.0f);
        atomicAdd(&g_deg[v.z], 1.0f);
        atomicAdd(&g_deg[v.w], 1.0f);
    }
    if (i == 0) {
        for (int e = EV * 4; e < E; ++e) atomicAdd(&g_deg[dst[e]], 1.0f);
    }
}

__global__ __launch_bounds__(256) void k_hd(int N) {
    int n = blockIdx.x * blockDim.x + threadIdx.x;
    if (n >= N) return;
    float v  = g_deg[n];
    float di = (v > 0.0f) ? rsqrtf(v) : 0.0f;
    g_dinv[n] = di;
    g_hd[n]   = g_h0[n] * di;
}

__global__ __launch_bounds__(256) void k_pass1(const int* __restrict__ src,
                                               const int* __restrict__ dst,
                                               int EV, int E) {
    int i = blockIdx.x * blockDim.x + threadIdx.x;
    if (i < EV) {
        int4 s = reinterpret_cast<const int4*>(src)[i];
        int4 d = reinterpret_cast<const int4*>(dst)[i];
        atomicAdd(&g_acc1[d.x], g_hd[s.x]);
        atomicAdd(&g_acc1[d.y], g_hd[s.y]);
        atomicAdd(&g_acc1[d.z], g_hd[s.z]);
        atomicAdd(&g_acc1[d.w], g_hd[s.w]);
    }
    if (i == 0) {
        for (int e = EV * 4; e < E; ++e) atomicAdd(&g_acc1[dst[e]], g_hd[src[e]]);
    }
}

__global__ __launch_bounds__(256) void k_s2(const float* __restrict__ W1,
                                            const float* __restrict__ b1,
                                            const float* __restrict__ W2, int N) {
    int n = blockIdx.x * blockDim.x + threadIdx.x;
    if (n >= N) return;
    float a = g_acc1[n] * g_dinv[n];  // conv1 segment value (b1 added per channel below)
    uint4 m = *reinterpret_cast<const uint4*>(g_mask2 + (size_t)n * 16);
    uint32_t mw[4] = {m.x, m.y, m.z, m.w};
    float s = 0.0f;
#pragma unroll
    for (int c = 0; c < 16; ++c) {
        float h = fmaf(a, __ldg(&W1[c]), __ldg(&b1[c]));
        h = fmaxf(h, 0.0f);
        if ((mw[c >> 2] >> ((c & 3) * 8)) & 1u)
            s = fmaf(h / 0.4f, __ldg(&W2[c]), s);
    }
    g_sd[n] = s * g_dinv[n];
}

__global__ __launch_bounds__(256) void k_pass2(const int* __restrict__ src,
                                               const int* __restrict__ dst,
                                               int EV, int E) {
    int i = blockIdx.x * blockDim.x + threadIdx.x;
    if (i < EV) {
        int4 s = reinterpret_cast<const int4*>(src)[i];
        int4 d = reinterpret_cast<const int4*>(dst)[i];
        atomicAdd(&g_acc2[d.x], g_sd[s.x]);
        atomicAdd(&g_acc2[d.y], g_sd[s.y]);
        atomicAdd(&g_acc2[d.z], g_sd[s.z]);
        atomicAdd(&g_acc2[d.w], g_sd[s.w]);
    }
    if (i == 0) {
        for (int e = EV * 4; e < E; ++e) atomicAdd(&g_acc2[dst[e]], g_sd[src[e]]);
    }
}

__global__ __launch_bounds__(256) void k_final(float* __restrict__ out,
                                               const float* __restrict__ b2, int N) {
    int n = blockIdx.x * blockDim.x + threadIdx.x;
    if (n >= N) return;
    out[n] = fmaf(g_acc2[n], g_dinv[n], __ldg(&b2[0]));
}

// ---------------- host ----------------

static void derive_keys(uint32_t& k1a, uint32_t& k1b, uint32_t& k2a, uint32_t& k2b) {
    // key(42) -> (0, 42); split(key, 2)
#if TF_VARIANT == 0
    // original: random_bits(32, (4,)): counts [0,1,2,3] -> halves (0,1) x (2,3)
    uint32_t a0, b0, a1, b1;
    tf2x32(0u, 42u, 0u, 2u, a0, b0);
    tf2x32(0u, 42u, 1u, 3u, a1, b1);
    k1a = a0; k1b = a1; k2a = b0; k2b = b1;
#else
    // partitionable "foldlike" split: key_i = full 64-bit output with counter i
    tf2x32(0u, 42u, 0u, 0u, k1a, k1b);
    tf2x32(0u, 42u, 0u, 1u, k2a, k2b);
#endif
}

extern "C" void kernel_launch(void* const* d_in, const int* in_sizes, int n_in,
                              void* d_out, int out_size) {
    const float* x   = (const float*)d_in[0];
    const int*   ei  = (const int*)d_in[1];      // edge_index is int32 (JAX x64 disabled)
    const float* W1  = (const float*)d_in[2];
    const float* b1  = (const float*)d_in[3];
    const float* W2  = (const float*)d_in[4];
    const float* b2  = (const float*)d_in[5];

    int N = in_sizes[0];
    int E = in_sizes[1] >> 1;                    // edge_index has 2*E int32 elements
    if (N > MAXN || N <= 0 || E <= 0) return;

    const int* src = ei;
    const int* dst = ei + E;

    uint32_t k1a, k1b, k2a, k2b;
    derive_keys(k1a, k1b, k2a, k2b);

    const int TPB = 256;
    int nb = (N + TPB - 1) / TPB;
    int M  = N * 16;
    int mb = (M + TPB - 1) / TPB;
    int EV = E / 4;                         // 4 edges per thread (int4 loads)
    int eb = (EV + TPB - 1) / TPB;
    if (eb == 0) eb = 1;

    k_init <<<nb, TPB>>>(x, N, k1a, k1b);
    k_mask2<<<mb, TPB>>>(M, k2a, k2b);
    k_deg  <<<eb, TPB>>>(dst, EV, E);
    k_hd   <<<nb, TPB>>>(N);
    k_pass1<<<eb, TPB>>>(src, dst, EV, E);
    k_s2   <<<nb, TPB>>>(W1, b1, W2, N);
    k_pass2<<<eb, TPB>>>(src, dst, EV, E);
    k_final<<<nb, TPB>>>((float*)d_out, b2, N);
}